// round 10
// baseline (speedup 1.0000x reference)
#include <cuda_runtime.h>
#include <cstdint>

#define NPTS   65536
#define NQ     1024
#define NBATCH 2
#define NS1    32
#define NS2    64
#define NOUT   128
#define NG     2048                 // mask words per query per radius
#define DPRE   16384                // prefix depth (points)
#define NGP    512                  // prefix words
#define NGT    (NG - NGP)           // 1536 tail words
#define WBLK_T (NGT / 16)           // 96 word-blocks, tail
#define SLOTCAP 1024                // max unfilled per batch (full coverage)

static __device__ float4   g_pts4[NBATCH * NPTS];        // (x,y,z,|p|^2)
static __device__ float4   g_w3t4[64 * 32];              // [c][lane] -> outputs o=lane+32k
static __device__ unsigned g_mask1[(size_t)NBATCH * NQ * NG];
static __device__ unsigned g_mask2[(size_t)NBATCH * NQ * NG];
static __device__ int      g_lists[NBATCH * NQ * 96];    // [l1(32)|l2(64)]
static __device__ int      g_filled[NBATCH * NQ];
static __device__ int      g_unf[NBATCH][SLOTCAP];
static __device__ int      g_unf_cnt[NBATCH];

__device__ __forceinline__ float sq3_rn(float x, float y, float z) {
    return __fadd_rn(__fadd_rn(__fmul_rn(x, x), __fmul_rn(y, y)), __fmul_rn(z, z));
}

__device__ __forceinline__ int query_flat_index(int q, int& b) {
    b = q >> 10;
    const int m = q & 1023;
    return (4 + 8 * (m >> 5)) * 256 + (4 + 8 * (m & 31));
}

__device__ __forceinline__ void radii(float& r1sq, float& r2sq) {
    r1sq = __fmul_rn(0.1f, 0.1f);
    r2sq = __fmul_rn(0.2f, 0.2f);
}

// d2 with the exact rounding order of the reference.
__device__ __forceinline__ float dist2_rn(float4 pt, float4 qp) {
    const float dot = __fadd_rn(__fadd_rn(__fmul_rn(pt.x, qp.x), __fmul_rn(pt.y, qp.y)),
                                __fmul_rn(pt.z, qp.z));
    return __fadd_rn(__fadd_rn(qp.w, pt.w), __fmul_rn(-2.0f, dot));
}

// Ballot-free mask words for FOUR queries sharing each point load.
__device__ __forceinline__ void make_mask_word4(
    const float4* __restrict__ P4, int pbase,
    const float4 qp[4], float r1sq, float r2sq,
    unsigned m1[4], unsigned m2[4])
{
#pragma unroll
    for (int s = 0; s < 4; s++) { m1[s] = 0u; m2[s] = 0u; }
#pragma unroll 8
    for (int i = 0; i < 32; i++) {
        const float4 p = __ldg(P4 + pbase + i);
#pragma unroll
        for (int s = 0; s < 4; s++) {
            const float d2 = dist2_rn(p, qp[s]);
            m1[s] |= (d2 < r1sq) ? (1u << i) : 0u;
            m2[s] |= (d2 < r2sq) ? (1u << i) : 0u;
        }
    }
}

// ---------------------------------------------------------------------------
// Kernel 0: pack pts -> float4(x,y,z,|p|^2); pack w3 -> g_w3t4; reset counters.
// ---------------------------------------------------------------------------
__global__ __launch_bounds__(256) void prep_kernel(const float* __restrict__ pts,
                                                   const float* __restrict__ w3) {
    const int blk = blockIdx.x;
    if (blk < NBATCH * NPTS / 256) {
        const int i = blk * 256 + threadIdx.x;
        const float x = __ldg(pts + 3 * i + 0);
        const float y = __ldg(pts + 3 * i + 1);
        const float z = __ldg(pts + 3 * i + 2);
        g_pts4[i] = make_float4(x, y, z, sq3_rn(x, y, z));
        if (i < NBATCH) g_unf_cnt[i] = 0;
    } else {
        const int i = (blk - NBATCH * NPTS / 256) * 256 + threadIdx.x;
        if (i < 64 * 32) {
            const int c = i >> 5, j = i & 31;
            g_w3t4[i] = make_float4(__ldg(w3 + (j +  0) * 64 + c),
                                    __ldg(w3 + (j + 32) * 64 + c),
                                    __ldg(w3 + (j + 64) * 64 + c),
                                    __ldg(w3 + (j + 96) * 64 + c));
        }
    }
}

// ---------------------------------------------------------------------------
// Kernel 1: prefix masks, ballot-free, 4 queries/thread.
// Block = 256 thr = 16 query-quads (64 queries) x 16 words.
// Grid = 32 qblk x 32 wblk = 1024 blocks.
// ---------------------------------------------------------------------------
__global__ __launch_bounds__(256) void mask_prefix_kernel() {
    const int bid  = blockIdx.x;
    const int qblk = bid >> 5;          // 0..31 (64 queries each)
    const int wblk = bid & 31;          // 0..31
    const int tid  = threadIdx.x;

    const int q0   = qblk * 64 + (tid & 15) * 4;
    const int word = wblk * 16 + (tid >> 4);
    const int b    = q0 >> 10;

    const float4* __restrict__ P4 = g_pts4 + (size_t)b * NPTS;
    float4 qp[4];
    int bb;
#pragma unroll
    for (int s = 0; s < 4; s++) qp[s] = __ldg(P4 + query_flat_index(q0 + s, bb));
    float r1sq, r2sq; radii(r1sq, r2sq);

    unsigned m1[4], m2[4];
    make_mask_word4(P4, word * 32, qp, r1sq, r2sq, m1, m2);

#pragma unroll
    for (int s = 0; s < 4; s++) {
        g_mask1[(size_t)(q0 + s) * NG + word] = m1[s];
        g_mask2[(size_t)(q0 + s) * NG + word] = m2[s];
    }
}

// ---------------------------------------------------------------------------
// Extract the first K set-bit indices (ascending) from nwords mask words.
// ---------------------------------------------------------------------------
__device__ __forceinline__ int extract_list(
    const unsigned* __restrict__ mask, int nwords, int K, int lane, int* __restrict__ list)
{
    int cnt = 0;
    for (int w0 = 0; w0 < nwords && cnt < K; w0 += 32) {
        const unsigned v = mask[w0 + lane];
        const int pc = __popc(v);
        int pre = pc;   // inclusive scan
#pragma unroll
        for (int d = 1; d < 32; d <<= 1) {
            const int t = __shfl_up_sync(0xffffffffu, pre, d);
            if (lane >= d) pre += t;
        }
        const int base = cnt + (pre - pc);
        unsigned vv = v; int k = 0;
        while (vv) {
            const int bit = __ffs(vv) - 1;
            const int p = base + k;
            if (p < K) list[p] = (w0 + lane) * 32 + bit;
            k++; vv &= vv - 1;
        }
        cnt += __shfl_sync(0xffffffffu, pre, 31);
    }
    return cnt;
}

__device__ __forceinline__ void write_lists_padded(
    int q, int lane, const int* __restrict__ l1, int c1, const int* __restrict__ l2, int c2)
{
    int* g1 = g_lists + q * 96;
    int* g2 = g1 + NS1;
    const int n1 = min(c1, NS1), n2 = min(c2, NS2);
    const int f1 = (n1 > 0) ? l1[0] : 0;
    const int f2 = (n2 > 0) ? l2[0] : 0;
    if (lane < NS1) g1[lane] = (lane < n1) ? l1[lane] : f1;
#pragma unroll
    for (int j = 0; j < 2; j++) {
        const int i = lane + j * 32;
        g2[i] = (i < n2) ? l2[i] : f2;
    }
}

// ---------------------------------------------------------------------------
// Kernel 2: extract from prefix masks; queue unfilled queries.
// ---------------------------------------------------------------------------
__global__ __launch_bounds__(256) void extract1_kernel() {
    __shared__ int ll1[8][NS1];
    __shared__ int ll2[8][NS2];

    const int lane = threadIdx.x & 31;
    const int wid  = threadIdx.x >> 5;
    const int q    = blockIdx.x * 8 + wid;
    const int b    = q >> 10;

    const int c1 = extract_list(g_mask1 + (size_t)q * NG, NGP, NS1, lane, ll1[wid]);
    const int c2 = extract_list(g_mask2 + (size_t)q * NG, NGP, NS2, lane, ll2[wid]);
    __syncwarp();

    if ((c1 >= NS1) && (c2 >= NS2)) {
        write_lists_padded(q, lane, ll1[wid], c1, ll2[wid], c2);
        if (lane == 0) g_filled[q] = 1;
    } else {
        if (lane == 0) {
            g_filled[q] = 0;
            const int pos = atomicAdd(&g_unf_cnt[b], 1);
            if (pos < SLOTCAP) g_unf[b][pos] = q;
        }
    }
}

// ---------------------------------------------------------------------------
// Kernel 3: tail masks, ballot-free, 4 slots/thread, tile-parallel.
// Block = 256 thr = 16 slot-quads (64 slots) x 16 words.
// Grid = NBATCH x (SLOTCAP/64) slotblk x WBLK_T wblk.
// ---------------------------------------------------------------------------
__global__ __launch_bounds__(256) void mask_tail_kernel() {
    const int bid     = blockIdx.x;
    const int perb    = (SLOTCAP / 64) * WBLK_T;
    const int b       = bid / perb;
    const int r       = bid % perb;
    const int slotblk = r / WBLK_T;
    const int wblk    = r % WBLK_T;

    const int cnt = g_unf_cnt[b];
    if (slotblk * 64 >= cnt) return;

    const int tid   = threadIdx.x;
    const int slot0 = slotblk * 64 + (tid & 15) * 4;
    const int word  = NGP + wblk * 16 + (tid >> 4);

    const float4* __restrict__ P4 = g_pts4 + (size_t)b * NPTS;

    bool   vs[4];
    int    qs[4];
    float4 qp[4];
    int bb;
#pragma unroll
    for (int s = 0; s < 4; s++) {
        const int slot = slot0 + s;
        vs[s] = (slot < cnt) && (slot < SLOTCAP);
        qs[s] = vs[s] ? g_unf[b][slot] : (b << 10);
        qp[s] = __ldg(P4 + query_flat_index(qs[s], bb));
    }
    float r1sq, r2sq; radii(r1sq, r2sq);

    unsigned m1[4], m2[4];
    make_mask_word4(P4, word * 32, qp, r1sq, r2sq, m1, m2);

#pragma unroll
    for (int s = 0; s < 4; s++) {
        if (vs[s]) {
            g_mask1[(size_t)qs[s] * NG + word] = m1[s];
            g_mask2[(size_t)qs[s] * NG + word] = m2[s];
        }
    }
}

// ---------------------------------------------------------------------------
// Kernel 4: extract over full mask range for unfilled queries.
// ---------------------------------------------------------------------------
__global__ __launch_bounds__(256) void extract2_kernel() {
    __shared__ int ll1[8][NS1];
    __shared__ int ll2[8][NS2];

    const int lane = threadIdx.x & 31;
    const int wid  = threadIdx.x >> 5;
    const int q    = blockIdx.x * 8 + wid;
    if (g_filled[q]) return;

    const int c1 = extract_list(g_mask1 + (size_t)q * NG, NG, NS1, lane, ll1[wid]);
    const int c2 = extract_list(g_mask2 + (size_t)q * NG, NG, NS2, lane, ll2[wid]);
    __syncwarp();
    write_lists_padded(q, lane, ll1[wid], c1, ll2[wid], c2);
}

// ---------------------------------------------------------------------------
// Kernel 5: MLP. R3 math (104 regs) but w3 read from pre-packed g_w3t4
// (no 33KB smem transpose preamble -> higher occupancy, fewer instructions).
// ---------------------------------------------------------------------------
#define INVC 0.9999950000374997f

__device__ __forceinline__ void mlp_point(
    float gx, float gy, float gz, float qx, float qy, float qz,
    const float* __restrict__ sA, const float* __restrict__ scA, const float* __restrict__ biA,
    const float* __restrict__ sB, const float* __restrict__ scB, const float* __restrict__ biB,
    float f[32])
{
    const float x0 = gx - qx, x1 = gy - qy, x2 = gz - qz;
    float a[16];
#pragma unroll
    for (int o = 0; o < 16; o++) {
        const float* w = sA + o * 6;
        float y = x0 * w[0];
        y = fmaf(x1, w[1], y);
        y = fmaf(x2, w[2], y);
        y = fmaf(gx, w[3], y);
        y = fmaf(gy, w[4], y);
        y = fmaf(gz, w[5], y);
        a[o] = fmaxf(fmaf(y, scA[o], biA[o]), 0.0f);
    }
#pragma unroll
    for (int o = 0; o < 32; o++) {
        const float* w = sB + o * 16;
        float y = 0.0f;
#pragma unroll
        for (int c = 0; c < 16; c++) y = fmaf(a[c], w[c], y);
        f[o] = fmaxf(f[o], fmaxf(fmaf(y, scB[o], biB[o]), 0.0f));
    }
}

__device__ __forceinline__ void warp_max32(float f[32]) {
#pragma unroll
    for (int o = 0; o < 32; o++) {
        float v = f[o];
        v = fmaxf(v, __shfl_xor_sync(0xffffffffu, v, 16));
        v = fmaxf(v, __shfl_xor_sync(0xffffffffu, v, 8));
        v = fmaxf(v, __shfl_xor_sync(0xffffffffu, v, 4));
        v = fmaxf(v, __shfl_xor_sync(0xffffffffu, v, 2));
        v = fmaxf(v, __shfl_xor_sync(0xffffffffu, v, 1));
        f[o] = v;
    }
}

__global__ __launch_bounds__(256) void mlp_kernel(
    const float* __restrict__ w1a, const float* __restrict__ g1a, const float* __restrict__ b1a,
    const float* __restrict__ w1b, const float* __restrict__ g1b, const float* __restrict__ b1b,
    const float* __restrict__ w2a, const float* __restrict__ g2a, const float* __restrict__ b2a,
    const float* __restrict__ w2b, const float* __restrict__ g2b, const float* __restrict__ b2b,
    const float* __restrict__ b3,
    float* __restrict__ out)
{
    __shared__ float s_w1a[96],  s_w2a[96];
    __shared__ float s_w1b[512], s_w2b[512];
    __shared__ float s_sc1a[16], s_bi1a[16], s_sc2a[16], s_bi2a[16];
    __shared__ float s_sc1b[32], s_bi1b[32], s_sc2b[32], s_bi2b[32];

    const int tid = threadIdx.x;
    for (int i = tid; i < 96; i += 256)  { s_w1a[i] = w1a[i]; s_w2a[i] = w2a[i]; }
    for (int i = tid; i < 512; i += 256) { s_w1b[i] = w1b[i]; s_w2b[i] = w2b[i]; }
    if (tid < 16) {
        s_sc1a[tid] = g1a[tid] * INVC; s_bi1a[tid] = b1a[tid];
        s_sc2a[tid] = g2a[tid] * INVC; s_bi2a[tid] = b2a[tid];
    } else if (tid < 48) {
        const int i = tid - 16;
        s_sc1b[i] = g1b[i] * INVC; s_bi1b[i] = b1b[i];
        s_sc2b[i] = g2b[i] * INVC; s_bi2b[i] = b2b[i];
    }
    __syncthreads();

    const int lane = tid & 31;
    const int wid  = tid >> 5;
    const int q    = blockIdx.x * 8 + wid;
    int b;
    const int fi = query_flat_index(q, b);

    const float4* __restrict__ P4 = g_pts4 + (size_t)b * NPTS;
    const float4 qp = __ldg(P4 + fi);
    const float qx = qp.x, qy = qp.y, qz = qp.z;

    const int* lst = g_lists + q * 96;
    const int i0 = __ldg(lst + lane);
    const int i1 = __ldg(lst + NS1 + lane);
    const int i2 = __ldg(lst + NS1 + 32 + lane);
    const float4 n0 = __ldg(P4 + i0);
    const float4 n1 = __ldg(P4 + i1);
    const float4 n2 = __ldg(P4 + i2);

    float acc0 = __ldg(b3 + lane +  0);
    float acc1 = __ldg(b3 + lane + 32);
    float acc2 = __ldg(b3 + lane + 64);
    float acc3 = __ldg(b3 + lane + 96);

    {   // branch 1 (S=32)
        float f[32];
#pragma unroll
        for (int o = 0; o < 32; o++) f[o] = 0.0f;
        mlp_point(n0.x, n0.y, n0.z, qx, qy, qz, s_w1a, s_sc1a, s_bi1a, s_w1b, s_sc1b, s_bi1b, f);
        warp_max32(f);
#pragma unroll
        for (int c = 0; c < 32; c++) {
            const float4 w = __ldg(g_w3t4 + c * 32 + lane);
            acc0 = fmaf(f[c], w.x, acc0);
            acc1 = fmaf(f[c], w.y, acc1);
            acc2 = fmaf(f[c], w.z, acc2);
            acc3 = fmaf(f[c], w.w, acc3);
        }
    }
    {   // branch 2 (S=64)
        float f[32];
#pragma unroll
        for (int o = 0; o < 32; o++) f[o] = 0.0f;
        mlp_point(n1.x, n1.y, n1.z, qx, qy, qz, s_w2a, s_sc2a, s_bi2a, s_w2b, s_sc2b, s_bi2b, f);
        mlp_point(n2.x, n2.y, n2.z, qx, qy, qz, s_w2a, s_sc2a, s_bi2a, s_w2b, s_sc2b, s_bi2b, f);
        warp_max32(f);
#pragma unroll
        for (int c = 0; c < 32; c++) {
            const float4 w = __ldg(g_w3t4 + (c + 32) * 32 + lane);
            acc0 = fmaf(f[c], w.x, acc0);
            acc1 = fmaf(f[c], w.y, acc1);
            acc2 = fmaf(f[c], w.z, acc2);
            acc3 = fmaf(f[c], w.w, acc3);
        }
    }
    const size_t ob = (size_t)q * NOUT;
    out[ob + lane +  0] = acc0;
    out[ob + lane + 32] = acc1;
    out[ob + lane + 64] = acc2;
    out[ob + lane + 96] = acc3;
}

extern "C" void kernel_launch(void* const* d_in, const int* in_sizes, int n_in,
                              void* d_out, int out_size) {
    const float* pts = (const float*)d_in[0];
    const float* w1a = (const float*)d_in[1];
    const float* g1a = (const float*)d_in[2];
    const float* b1a = (const float*)d_in[3];
    const float* w1b = (const float*)d_in[4];
    const float* g1b = (const float*)d_in[5];
    const float* b1b = (const float*)d_in[6];
    const float* w2a = (const float*)d_in[7];
    const float* g2a = (const float*)d_in[8];
    const float* b2a = (const float*)d_in[9];
    const float* w2b = (const float*)d_in[10];
    const float* g2b = (const float*)d_in[11];
    const float* b2b = (const float*)d_in[12];
    const float* w3  = (const float*)d_in[13];
    const float* b3  = (const float*)d_in[14];
    float* out = (float*)d_out;

    prep_kernel<<<NBATCH * NPTS / 256 + 8, 256>>>(pts, w3);
    mask_prefix_kernel<<<32 * 32, 256>>>();
    extract1_kernel<<<NBATCH * NQ / 8, 256>>>();
    mask_tail_kernel<<<NBATCH * (SLOTCAP / 64) * WBLK_T, 256>>>();
    extract2_kernel<<<NBATCH * NQ / 8, 256>>>();
    mlp_kernel<<<NBATCH * NQ / 8, 256>>>(w1a, g1a, b1a, w1b, g1b, b1b,
                                         w2a, g2a, b2a, w2b, g2b, b2b, b3, out);
}

// round 11
// speedup vs baseline: 1.4404x; 1.4404x over previous
#include <cuda_runtime.h>
#include <cstdint>

#define NPTS   65536
#define NQ     1024
#define NBATCH 2
#define NS1    32
#define NS2    64
#define NOUT   128
#define DPRE   16384                // prefix depth (points)
#define NGP    (DPRE / 32)          // 512 prefix mask words
#define NGT    ((NPTS - DPRE) / 32) // 1536 tail mask words
#define NCELL  1000                 // 10x10x10 cells
#define REGCAP 49152                // max points per (batch,region) slab
#define RP     0.201f               // r2 + safety margin for cell boxes

static __device__ float4 g_pts4[NBATCH * NPTS];          // (x,y,z,|p|^2) by original idx
static __device__ float4 g_w3t4[64 * 32];                // [c][lane] -> outputs o=lane+32k
static __device__ int    g_hist[NBATCH * 2][NCELL];      // per (batch,region) cell counts
static __device__ int    g_cellstart[NBATCH * 2][NCELL + 1];
static __device__ int    g_cursor[NBATCH * 2][NCELL];
static __device__ float4 g_sp[(size_t)NBATCH * 2 * REGCAP];  // binned points
static __device__ int    g_si[(size_t)NBATCH * 2 * REGCAP];  // original batch-local idx
static __device__ int    g_lists[NBATCH * NQ * 96];      // [l1(32)|l2(64)]
static __device__ int    g_state[NBATCH * NQ * 2];       // prefix counts c1,c2
static __device__ int    g_filled[NBATCH * NQ];

__device__ __forceinline__ float sq3_rn(float x, float y, float z) {
    return __fadd_rn(__fadd_rn(__fmul_rn(x, x), __fmul_rn(y, y)), __fmul_rn(z, z));
}

__device__ __forceinline__ int query_flat_index(int q, int& b) {
    b = q >> 10;
    const int m = q & 1023;
    return (4 + 8 * (m >> 5)) * 256 + (4 + 8 * (m & 31));
}

__device__ __forceinline__ void radii(float& r1sq, float& r2sq) {
    r1sq = __fmul_rn(0.1f, 0.1f);
    r2sq = __fmul_rn(0.2f, 0.2f);
}

// d2 with the exact rounding order of the reference.
__device__ __forceinline__ float dist2_rn(float4 pt, float4 qp) {
    const float dot = __fadd_rn(__fadd_rn(__fmul_rn(pt.x, qp.x), __fmul_rn(pt.y, qp.y)),
                                __fmul_rn(pt.z, qp.z));
    return __fadd_rn(__fadd_rn(qp.w, pt.w), __fmul_rn(-2.0f, dot));
}

__device__ __forceinline__ int cell_of(float x, float y, float z) {
    const int cx = min(9, (int)(x * 10.0f));
    const int cy = min(9, (int)(y * 10.0f));
    const int cz = min(9, (int)(z * 10.0f));
    return (cz * 10 + cy) * 10 + cx;
}

// ---------------------------------------------------------------------------
// Kernel 0: pack pts; histogram cells; pack w3. (g_hist pre-zeroed by memset.)
// ---------------------------------------------------------------------------
__global__ __launch_bounds__(256) void prep_kernel(const float* __restrict__ pts,
                                                   const float* __restrict__ w3) {
    const int blk = blockIdx.x;
    if (blk < NBATCH * NPTS / 256) {
        const int i = blk * 256 + threadIdx.x;   // 0..131071
        const float x = __ldg(pts + 3 * i + 0);
        const float y = __ldg(pts + 3 * i + 1);
        const float z = __ldg(pts + 3 * i + 2);
        g_pts4[i] = make_float4(x, y, z, sq3_rn(x, y, z));
        const int b = i >> 16, pi = i & (NPTS - 1);
        const int r = (pi < DPRE) ? 0 : 1;
        atomicAdd(&g_hist[b * 2 + r][cell_of(x, y, z)], 1);
    } else {
        const int i = (blk - NBATCH * NPTS / 256) * 256 + threadIdx.x;
        if (i < 64 * 32) {
            const int c = i >> 5, j = i & 31;
            g_w3t4[i] = make_float4(__ldg(w3 + (j +  0) * 64 + c),
                                    __ldg(w3 + (j + 32) * 64 + c),
                                    __ldg(w3 + (j + 64) * 64 + c),
                                    __ldg(w3 + (j + 96) * 64 + c));
        }
    }
}

// ---------------------------------------------------------------------------
// Kernel 1: exclusive scan of per-slab histograms (one 1024-thread block each).
// ---------------------------------------------------------------------------
__global__ __launch_bounds__(1024) void scan_kernel() {
    __shared__ int buf[2][1024];
    const int br = blockIdx.x, tid = threadIdx.x;
    int v = (tid < NCELL) ? g_hist[br][tid] : 0;
    buf[0][tid] = v;
    __syncthreads();
    int src = 0;
    for (int d = 1; d < 1024; d <<= 1) {
        int t = buf[src][tid];
        if (tid >= d) t += buf[src][tid - d];
        __syncthreads();
        buf[src ^ 1][tid] = t;
        src ^= 1;
        __syncthreads();
    }
    const int excl = (tid == 0) ? 0 : buf[src][tid - 1];
    if (tid <= NCELL) g_cellstart[br][tid] = excl;   // entry NCELL = total
    if (tid < NCELL)  g_cursor[br][tid] = excl;
}

// ---------------------------------------------------------------------------
// Kernel 2: scatter points into binned slabs (order within cell irrelevant).
// ---------------------------------------------------------------------------
__global__ __launch_bounds__(256) void scatter_kernel() {
    const int i = blockIdx.x * 256 + threadIdx.x;   // 0..131071
    const int b = i >> 16, pi = i & (NPTS - 1);
    const float4 p = g_pts4[i];
    const int r = (pi < DPRE) ? 0 : 1;
    const int br = b * 2 + r;
    const int pos = atomicAdd(&g_cursor[br][cell_of(p.x, p.y, p.z)], 1);
    g_sp[(size_t)br * REGCAP + pos] = p;
    g_si[(size_t)br * REGCAP + pos] = pi;
}

// ---------------------------------------------------------------------------
// Extract/append first-K set bits (ascending) starting from count cnt0.
// idx_base added to emitted indices. Warp-collective. Returns total count seen.
// ---------------------------------------------------------------------------
__device__ __forceinline__ int extract_append(
    const unsigned* __restrict__ mask, int nwords, int K, int lane,
    int* __restrict__ list, int cnt0, int idx_base)
{
    int cnt = cnt0;
    for (int w0 = 0; w0 < nwords && cnt < K; w0 += 32) {
        const unsigned v = mask[w0 + lane];
        const int pc = __popc(v);
        int pre = pc;   // inclusive scan of popcounts
#pragma unroll
        for (int d = 1; d < 32; d <<= 1) {
            const int t = __shfl_up_sync(0xffffffffu, pre, d);
            if (lane >= d) pre += t;
        }
        const int base = cnt + (pre - pc);
        unsigned vv = v; int k = 0;
        while (vv) {
            const int bit = __ffs(vv) - 1;
            const int p = base + k;
            if (p < K) list[p] = idx_base + (w0 + lane) * 32 + bit;
            k++; vv &= vv - 1;
        }
        cnt += __shfl_sync(0xffffffffu, pre, 31);
    }
    return cnt;
}

__device__ __forceinline__ void write_lists_padded(
    int q, int lane, const int* __restrict__ l1, int c1, const int* __restrict__ l2, int c2)
{
    int* g1 = g_lists + q * 96;
    int* g2 = g1 + NS1;
    const int n1 = min(c1, NS1), n2 = min(c2, NS2);
    const int f1 = (n1 > 0) ? l1[0] : 0;
    const int f2 = (n2 > 0) ? l2[0] : 0;
    if (lane < NS1) g1[lane] = (lane < n1) ? l1[lane] : f1;
#pragma unroll
    for (int j = 0; j < 2; j++) {
        const int i = lane + j * 32;
        g2[i] = (i < n2) ? l2[i] : f2;
    }
}

// Shared candidate-loop: test all binned points in the query's cell box,
// setting bits (idx - idx_base) in the smem masks.
__device__ __forceinline__ void sparse_mask_build(
    int br, float4 qp, float r1sq, float r2sq, int idx_base,
    int wid, int lane, unsigned* __restrict__ sm1, unsigned* __restrict__ sm2)
{
    const int cx0 = max(0, (int)((qp.x - RP) * 10.0f));
    const int cx1 = min(9, (int)((qp.x + RP) * 10.0f));
    const int cy0 = max(0, (int)((qp.y - RP) * 10.0f));
    const int cy1 = min(9, (int)((qp.y + RP) * 10.0f));
    const int cz0 = max(0, (int)((qp.z - RP) * 10.0f));
    const int cz1 = min(9, (int)((qp.z + RP) * 10.0f));
    const int ny = cy1 - cy0 + 1, nzy = (cz1 - cz0 + 1) * ny;

    const float4* __restrict__ sp = g_sp + (size_t)br * REGCAP;
    const int*    __restrict__ si = g_si + (size_t)br * REGCAP;
    const int*    __restrict__ cs = g_cellstart[br];

    for (int p = wid; p < nzy; p += 8) {
        const int cz = cz0 + p / ny, cy = cy0 + p % ny;
        const int row = (cz * 10 + cy) * 10;
        const int s = cs[row + cx0];
        const int e = cs[row + cx1 + 1];   // x-cells contiguous in flat order
        for (int j = s + lane; j < e; j += 32) {
            const float4 pt = __ldg(sp + j);
            const int idx = __ldg(si + j);
            const float d2 = dist2_rn(pt, qp);
            if (d2 < r2sq) {
                const int bp = idx - idx_base;
                atomicOr(&sm2[bp >> 5], 1u << (bp & 31));
                if (d2 < r1sq) atomicOr(&sm1[bp >> 5], 1u << (bp & 31));
            }
        }
    }
}

// ---------------------------------------------------------------------------
// Kernel 3: prefix masks (sparse) + fused extraction. One block per query.
// ---------------------------------------------------------------------------
__global__ __launch_bounds__(256) void sparse_prefix_kernel() {
    __shared__ unsigned sm1[NGP], sm2[NGP];
    __shared__ int sl1[NS1], sl2[NS2], scnt[2];

    const int tid = threadIdx.x, lane = tid & 31, wid = tid >> 5;
    const int q = blockIdx.x, b = q >> 10;
    for (int i = tid; i < NGP; i += 256) { sm1[i] = 0u; sm2[i] = 0u; }
    int bb;
    const int fi = query_flat_index(q, bb);
    const float4 qp = __ldg(g_pts4 + (size_t)b * NPTS + fi);
    float r1sq, r2sq; radii(r1sq, r2sq);
    __syncthreads();

    sparse_mask_build(b * 2 + 0, qp, r1sq, r2sq, 0, wid, lane, sm1, sm2);
    __syncthreads();

    if (wid == 0)      { const int c = extract_append(sm1, NGP, NS1, lane, sl1, 0, 0); if (lane == 0) scnt[0] = c; }
    else if (wid == 1) { const int c = extract_append(sm2, NGP, NS2, lane, sl2, 0, 0); if (lane == 0) scnt[1] = c; }
    __syncthreads();

    const int c1 = scnt[0], c2 = scnt[1];
    if (wid == 0) {
        write_lists_padded(q, lane, sl1, c1, sl2, c2);
        if (lane == 0) {
            g_state[q * 2 + 0] = min(c1, NS1);
            g_state[q * 2 + 1] = min(c2, NS2);
            g_filled[q] = (c1 >= NS1 && c2 >= NS2) ? 1 : 0;
        }
    }
}

// ---------------------------------------------------------------------------
// Kernel 4: tail masks (sparse) + fused append for unfilled queries only.
// ---------------------------------------------------------------------------
__global__ __launch_bounds__(256) void sparse_tail_kernel() {
    const int q = blockIdx.x;
    if (g_filled[q]) return;

    __shared__ unsigned tm1[NGT], tm2[NGT];   // 12 KB
    __shared__ int scnt[2];

    const int tid = threadIdx.x, lane = tid & 31, wid = tid >> 5;
    const int b = q >> 10;
    for (int i = tid; i < NGT; i += 256) { tm1[i] = 0u; tm2[i] = 0u; }
    int bb;
    const int fi = query_flat_index(q, bb);
    const float4 qp = __ldg(g_pts4 + (size_t)b * NPTS + fi);
    float r1sq, r2sq; radii(r1sq, r2sq);
    __syncthreads();

    sparse_mask_build(b * 2 + 1, qp, r1sq, r2sq, DPRE, wid, lane, tm1, tm2);
    __syncthreads();

    int* g1 = g_lists + q * 96;
    int* g2 = g1 + NS1;
    const int c1 = g_state[q * 2 + 0];
    const int c2 = g_state[q * 2 + 1];
    if (wid == 0)      { const int t = extract_append(tm1, NGT, NS1, lane, g1, c1, DPRE); if (lane == 0) scnt[0] = min(t, NS1); }
    else if (wid == 1) { const int t = extract_append(tm2, NGT, NS2, lane, g2, c2, DPRE); if (lane == 0) scnt[1] = min(t, NS2); }
    __syncthreads();

    if (wid == 0) {
        const int t1 = scnt[0];
        const int f1 = (t1 > 0) ? g1[0] : 0;
        for (int j = t1 + lane; j < NS1; j += 32) g1[j] = f1;
    } else if (wid == 1) {
        const int t2 = scnt[1];
        const int f2 = (t2 > 0) ? g2[0] : 0;
        for (int j = t2 + lane; j < NS2; j += 32) g2[j] = f2;
    }
}

// ---------------------------------------------------------------------------
// Kernel 5: MLP (R10 version — w3 pre-packed, no smem transpose preamble).
// ---------------------------------------------------------------------------
#define INVC 0.9999950000374997f

__device__ __forceinline__ void mlp_point(
    float gx, float gy, float gz, float qx, float qy, float qz,
    const float* __restrict__ sA, const float* __restrict__ scA, const float* __restrict__ biA,
    const float* __restrict__ sB, const float* __restrict__ scB, const float* __restrict__ biB,
    float f[32])
{
    const float x0 = gx - qx, x1 = gy - qy, x2 = gz - qz;
    float a[16];
#pragma unroll
    for (int o = 0; o < 16; o++) {
        const float* w = sA + o * 6;
        float y = x0 * w[0];
        y = fmaf(x1, w[1], y);
        y = fmaf(x2, w[2], y);
        y = fmaf(gx, w[3], y);
        y = fmaf(gy, w[4], y);
        y = fmaf(gz, w[5], y);
        a[o] = fmaxf(fmaf(y, scA[o], biA[o]), 0.0f);
    }
#pragma unroll
    for (int o = 0; o < 32; o++) {
        const float* w = sB + o * 16;
        float y = 0.0f;
#pragma unroll
        for (int c = 0; c < 16; c++) y = fmaf(a[c], w[c], y);
        f[o] = fmaxf(f[o], fmaxf(fmaf(y, scB[o], biB[o]), 0.0f));
    }
}

__device__ __forceinline__ void warp_max32(float f[32]) {
#pragma unroll
    for (int o = 0; o < 32; o++) {
        float v = f[o];
        v = fmaxf(v, __shfl_xor_sync(0xffffffffu, v, 16));
        v = fmaxf(v, __shfl_xor_sync(0xffffffffu, v, 8));
        v = fmaxf(v, __shfl_xor_sync(0xffffffffu, v, 4));
        v = fmaxf(v, __shfl_xor_sync(0xffffffffu, v, 2));
        v = fmaxf(v, __shfl_xor_sync(0xffffffffu, v, 1));
        f[o] = v;
    }
}

__global__ __launch_bounds__(256) void mlp_kernel(
    const float* __restrict__ w1a, const float* __restrict__ g1a, const float* __restrict__ b1a,
    const float* __restrict__ w1b, const float* __restrict__ g1b, const float* __restrict__ b1b,
    const float* __restrict__ w2a, const float* __restrict__ g2a, const float* __restrict__ b2a,
    const float* __restrict__ w2b, const float* __restrict__ g2b, const float* __restrict__ b2b,
    const float* __restrict__ b3,
    float* __restrict__ out)
{
    __shared__ float s_w1a[96],  s_w2a[96];
    __shared__ float s_w1b[512], s_w2b[512];
    __shared__ float s_sc1a[16], s_bi1a[16], s_sc2a[16], s_bi2a[16];
    __shared__ float s_sc1b[32], s_bi1b[32], s_sc2b[32], s_bi2b[32];

    const int tid = threadIdx.x;
    for (int i = tid; i < 96; i += 256)  { s_w1a[i] = w1a[i]; s_w2a[i] = w2a[i]; }
    for (int i = tid; i < 512; i += 256) { s_w1b[i] = w1b[i]; s_w2b[i] = w2b[i]; }
    if (tid < 16) {
        s_sc1a[tid] = g1a[tid] * INVC; s_bi1a[tid] = b1a[tid];
        s_sc2a[tid] = g2a[tid] * INVC; s_bi2a[tid] = b2a[tid];
    } else if (tid < 48) {
        const int i = tid - 16;
        s_sc1b[i] = g1b[i] * INVC; s_bi1b[i] = b1b[i];
        s_sc2b[i] = g2b[i] * INVC; s_bi2b[i] = b2b[i];
    }
    __syncthreads();

    const int lane = tid & 31;
    const int wid  = tid >> 5;
    const int q    = blockIdx.x * 8 + wid;
    int b;
    const int fi = query_flat_index(q, b);

    const float4* __restrict__ P4 = g_pts4 + (size_t)b * NPTS;
    const float4 qp = __ldg(P4 + fi);
    const float qx = qp.x, qy = qp.y, qz = qp.z;

    const int* lst = g_lists + q * 96;
    const int i0 = __ldg(lst + lane);
    const int i1 = __ldg(lst + NS1 + lane);
    const int i2 = __ldg(lst + NS1 + 32 + lane);
    const float4 n0 = __ldg(P4 + i0);
    const float4 n1 = __ldg(P4 + i1);
    const float4 n2 = __ldg(P4 + i2);

    float acc0 = __ldg(b3 + lane +  0);
    float acc1 = __ldg(b3 + lane + 32);
    float acc2 = __ldg(b3 + lane + 64);
    float acc3 = __ldg(b3 + lane + 96);

    {   // branch 1 (S=32)
        float f[32];
#pragma unroll
        for (int o = 0; o < 32; o++) f[o] = 0.0f;
        mlp_point(n0.x, n0.y, n0.z, qx, qy, qz, s_w1a, s_sc1a, s_bi1a, s_w1b, s_sc1b, s_bi1b, f);
        warp_max32(f);
#pragma unroll
        for (int c = 0; c < 32; c++) {
            const float4 w = __ldg(g_w3t4 + c * 32 + lane);
            acc0 = fmaf(f[c], w.x, acc0);
            acc1 = fmaf(f[c], w.y, acc1);
            acc2 = fmaf(f[c], w.z, acc2);
            acc3 = fmaf(f[c], w.w, acc3);
        }
    }
    {   // branch 2 (S=64)
        float f[32];
#pragma unroll
        for (int o = 0; o < 32; o++) f[o] = 0.0f;
        mlp_point(n1.x, n1.y, n1.z, qx, qy, qz, s_w2a, s_sc2a, s_bi2a, s_w2b, s_sc2b, s_bi2b, f);
        mlp_point(n2.x, n2.y, n2.z, qx, qy, qz, s_w2a, s_sc2a, s_bi2a, s_w2b, s_sc2b, s_bi2b, f);
        warp_max32(f);
#pragma unroll
        for (int c = 0; c < 32; c++) {
            const float4 w = __ldg(g_w3t4 + (c + 32) * 32 + lane);
            acc0 = fmaf(f[c], w.x, acc0);
            acc1 = fmaf(f[c], w.y, acc1);
            acc2 = fmaf(f[c], w.z, acc2);
            acc3 = fmaf(f[c], w.w, acc3);
        }
    }
    const size_t ob = (size_t)q * NOUT;
    out[ob + lane +  0] = acc0;
    out[ob + lane + 32] = acc1;
    out[ob + lane + 64] = acc2;
    out[ob + lane + 96] = acc3;
}

extern "C" void kernel_launch(void* const* d_in, const int* in_sizes, int n_in,
                              void* d_out, int out_size) {
    const float* pts = (const float*)d_in[0];
    const float* w1a = (const float*)d_in[1];
    const float* g1a = (const float*)d_in[2];
    const float* b1a = (const float*)d_in[3];
    const float* w1b = (const float*)d_in[4];
    const float* g1b = (const float*)d_in[5];
    const float* b1b = (const float*)d_in[6];
    const float* w2a = (const float*)d_in[7];
    const float* g2a = (const float*)d_in[8];
    const float* b2a = (const float*)d_in[9];
    const float* w2b = (const float*)d_in[10];
    const float* g2b = (const float*)d_in[11];
    const float* b2b = (const float*)d_in[12];
    const float* w3  = (const float*)d_in[13];
    const float* b3  = (const float*)d_in[14];
    float* out = (float*)d_out;

    static void* hist_ptr = nullptr;
    if (!hist_ptr) cudaGetSymbolAddress(&hist_ptr, g_hist);

    cudaMemsetAsync(hist_ptr, 0, sizeof(int) * NBATCH * 2 * NCELL);
    prep_kernel<<<NBATCH * NPTS / 256 + 8, 256>>>(pts, w3);
    scan_kernel<<<NBATCH * 2, 1024>>>();
    scatter_kernel<<<NBATCH * NPTS / 256, 256>>>();
    sparse_prefix_kernel<<<NBATCH * NQ, 256>>>();
    sparse_tail_kernel<<<NBATCH * NQ, 256>>>();
    mlp_kernel<<<NBATCH * NQ / 8, 256>>>(w1a, g1a, b1a, w1b, g1b, b1b,
                                         w2a, g2a, b2a, w2b, g2b, b2b, b3, out);
}

// round 12
// speedup vs baseline: 1.5166x; 1.0529x over previous
#include <cuda_runtime.h>
#include <cstdint>

#define NPTS   65536
#define NQ     1024
#define NBATCH 2
#define NS1    32
#define NS2    64
#define NOUT   128
#define DPRE   16384                // prefix depth (points)
#define NGP    (DPRE / 32)          // 512 prefix mask words
#define NGT    ((NPTS - DPRE) / 32) // 1536 tail mask words
#define NCELL  1000                 // 10x10x10 cells
#define REGCAP 49152                // max points per (batch,region) slab
#define RP     0.201f               // r2 + safety margin for cell boxes

static __device__ float4 g_pts4[NBATCH * NPTS];          // (x,y,z,|p|^2) by original idx
static __device__ float4 g_w3t4[64 * 32];                // [c][lane] -> outputs o=lane+32k
static __device__ int    g_hist[NBATCH * 2][NCELL];
static __device__ int    g_cellstart[NBATCH * 2][NCELL + 1];
static __device__ int    g_cursor[NBATCH * 2][NCELL];
static __device__ float4 g_sp[(size_t)NBATCH * 2 * REGCAP];  // binned points
static __device__ int    g_si[(size_t)NBATCH * 2 * REGCAP];  // original batch-local idx
static __device__ int    g_lists[NBATCH * NQ * 96];      // [l1(32)|l2(64)]

__device__ __forceinline__ float sq3_rn(float x, float y, float z) {
    return __fadd_rn(__fadd_rn(__fmul_rn(x, x), __fmul_rn(y, y)), __fmul_rn(z, z));
}

__device__ __forceinline__ int query_flat_index(int q, int& b) {
    b = q >> 10;
    const int m = q & 1023;
    return (4 + 8 * (m >> 5)) * 256 + (4 + 8 * (m & 31));
}

__device__ __forceinline__ void radii(float& r1sq, float& r2sq) {
    r1sq = __fmul_rn(0.1f, 0.1f);
    r2sq = __fmul_rn(0.2f, 0.2f);
}

// d2 with the exact rounding order of the reference.
__device__ __forceinline__ float dist2_rn(float4 pt, float4 qp) {
    const float dot = __fadd_rn(__fadd_rn(__fmul_rn(pt.x, qp.x), __fmul_rn(pt.y, qp.y)),
                                __fmul_rn(pt.z, qp.z));
    return __fadd_rn(__fadd_rn(qp.w, pt.w), __fmul_rn(-2.0f, dot));
}

__device__ __forceinline__ int cell_of(float x, float y, float z) {
    const int cx = min(9, (int)(x * 10.0f));
    const int cy = min(9, (int)(y * 10.0f));
    const int cz = min(9, (int)(z * 10.0f));
    return (cz * 10 + cy) * 10 + cx;
}

// ---------------------------------------------------------------------------
// Kernel 0: pack pts; histogram cells; pack w3. (g_hist pre-zeroed by memset.)
// ---------------------------------------------------------------------------
__global__ __launch_bounds__(256) void prep_kernel(const float* __restrict__ pts,
                                                   const float* __restrict__ w3) {
    const int blk = blockIdx.x;
    if (blk < NBATCH * NPTS / 256) {
        const int i = blk * 256 + threadIdx.x;   // 0..131071
        const float x = __ldg(pts + 3 * i + 0);
        const float y = __ldg(pts + 3 * i + 1);
        const float z = __ldg(pts + 3 * i + 2);
        g_pts4[i] = make_float4(x, y, z, sq3_rn(x, y, z));
        const int b = i >> 16, pi = i & (NPTS - 1);
        const int r = (pi < DPRE) ? 0 : 1;
        atomicAdd(&g_hist[b * 2 + r][cell_of(x, y, z)], 1);
    } else {
        const int i = (blk - NBATCH * NPTS / 256) * 256 + threadIdx.x;
        if (i < 64 * 32) {
            const int c = i >> 5, j = i & 31;
            g_w3t4[i] = make_float4(__ldg(w3 + (j +  0) * 64 + c),
                                    __ldg(w3 + (j + 32) * 64 + c),
                                    __ldg(w3 + (j + 64) * 64 + c),
                                    __ldg(w3 + (j + 96) * 64 + c));
        }
    }
}

// ---------------------------------------------------------------------------
// Kernel 1: exclusive scan of per-slab histograms.
// ---------------------------------------------------------------------------
__global__ __launch_bounds__(1024) void scan_kernel() {
    __shared__ int buf[2][1024];
    const int br = blockIdx.x, tid = threadIdx.x;
    int v = (tid < NCELL) ? g_hist[br][tid] : 0;
    buf[0][tid] = v;
    __syncthreads();
    int src = 0;
    for (int d = 1; d < 1024; d <<= 1) {
        int t = buf[src][tid];
        if (tid >= d) t += buf[src][tid - d];
        __syncthreads();
        buf[src ^ 1][tid] = t;
        src ^= 1;
        __syncthreads();
    }
    const int excl = (tid == 0) ? 0 : buf[src][tid - 1];
    if (tid <= NCELL) g_cellstart[br][tid] = excl;
    if (tid < NCELL)  g_cursor[br][tid] = excl;
}

// ---------------------------------------------------------------------------
// Kernel 2: scatter points into binned slabs.
// ---------------------------------------------------------------------------
__global__ __launch_bounds__(256) void scatter_kernel() {
    const int i = blockIdx.x * 256 + threadIdx.x;   // 0..131071
    const int b = i >> 16, pi = i & (NPTS - 1);
    const float4 p = g_pts4[i];
    const int r = (pi < DPRE) ? 0 : 1;
    const int br = b * 2 + r;
    const int pos = atomicAdd(&g_cursor[br][cell_of(p.x, p.y, p.z)], 1);
    g_sp[(size_t)br * REGCAP + pos] = p;
    g_si[(size_t)br * REGCAP + pos] = pi;
}

// ---------------------------------------------------------------------------
// Block-parallel first-K extraction: all 8 warps emit set bits at exact global
// positions (ascending index order). Returns total bit count (uncapped).
// WPL = words per lane (warp covers WPL*32 consecutive words).
// ---------------------------------------------------------------------------
template <int WPL>
__device__ __forceinline__ int block_extract(
    const unsigned* __restrict__ mask, int K, int lane, int wid,
    int* __restrict__ list, int cnt0, int idx_base, int* __restrict__ s_tot)
{
    const int base_word = wid * (WPL * 32);
    int tot = 0;
#pragma unroll
    for (int j = 0; j < WPL; j++) tot += __popc(mask[base_word + j * 32 + lane]);
#pragma unroll
    for (int d = 16; d; d >>= 1) tot += __shfl_xor_sync(0xffffffffu, tot, d);
    if (lane == 0) s_tot[wid] = tot;
    __syncthreads();

    int base = cnt0, total = cnt0;
#pragma unroll
    for (int v = 0; v < 8; v++) {
        const int t = s_tot[v];
        if (v < wid) base += t;
        total += t;
    }

    int running = base;
#pragma unroll
    for (int j = 0; j < WPL; j++) {
        const int w = base_word + j * 32 + lane;
        const unsigned v = mask[w];
        const int pc = __popc(v);
        int pre = pc;
#pragma unroll
        for (int d = 1; d < 32; d <<= 1) {
            const int t = __shfl_up_sync(0xffffffffu, pre, d);
            if (lane >= d) pre += t;
        }
        int p = running + (pre - pc);
        unsigned vv = v;
        while (vv && p < K) {
            const int bit = __ffs(vv) - 1;
            list[p] = idx_base + w * 32 + bit;
            p++; vv &= vv - 1;
        }
        running += __shfl_sync(0xffffffffu, pre, 31);
    }
    __syncthreads();   // s_tot reusable by the next call
    return total;
}

// Candidate loop over the query's cell box; set bits (idx - idx_base) in masks.
__device__ __forceinline__ void sparse_mask_build(
    int br, float4 qp, float r1sq, float r2sq, int idx_base,
    int wid, int lane, unsigned* __restrict__ sm1, unsigned* __restrict__ sm2)
{
    const int cx0 = max(0, (int)((qp.x - RP) * 10.0f));
    const int cx1 = min(9, (int)((qp.x + RP) * 10.0f));
    const int cy0 = max(0, (int)((qp.y - RP) * 10.0f));
    const int cy1 = min(9, (int)((qp.y + RP) * 10.0f));
    const int cz0 = max(0, (int)((qp.z - RP) * 10.0f));
    const int cz1 = min(9, (int)((qp.z + RP) * 10.0f));
    const int ny = cy1 - cy0 + 1, nzy = (cz1 - cz0 + 1) * ny;

    const float4* __restrict__ sp = g_sp + (size_t)br * REGCAP;
    const int*    __restrict__ si = g_si + (size_t)br * REGCAP;
    const int*    __restrict__ cs = g_cellstart[br];

    for (int p = wid; p < nzy; p += 8) {
        const int cz = cz0 + p / ny, cy = cy0 + p % ny;
        const int row = (cz * 10 + cy) * 10;
        const int s = cs[row + cx0];
        const int e = cs[row + cx1 + 1];   // x-cells contiguous in flat order
        for (int j = s + lane; j < e; j += 32) {
            const float4 pt = __ldg(sp + j);
            const int idx = __ldg(si + j);
            const float d2 = dist2_rn(pt, qp);
            if (d2 < r2sq) {
                const int bp = idx - idx_base;
                atomicOr(&sm2[bp >> 5], 1u << (bp & 31));
                if (d2 < r1sq) atomicOr(&sm1[bp >> 5], 1u << (bp & 31));
            }
        }
    }
}

// ---------------------------------------------------------------------------
// Kernel 3: fused ball query. One block per query: prefix masks + parallel
// extract; only if unfilled, continue into the tail region (mask buffer
// reused). Single padded write of both lists at the end.
// ---------------------------------------------------------------------------
__global__ __launch_bounds__(256) void ballquery_kernel() {
    __shared__ unsigned sm1[NGT], sm2[NGT];   // 12 KB, prefix uses first NGP
    __shared__ int sl1[NS1], sl2[NS2];
    __shared__ int s_tot[8];

    const int tid = threadIdx.x, lane = tid & 31, wid = tid >> 5;
    const int q = blockIdx.x, b = q >> 10;
    int bb;
    const int fi = query_flat_index(q, bb);
    const float4 qp = __ldg(g_pts4 + (size_t)b * NPTS + fi);
    float r1sq, r2sq; radii(r1sq, r2sq);

    for (int i = tid; i < NGP; i += 256) { sm1[i] = 0u; sm2[i] = 0u; }
    __syncthreads();

    sparse_mask_build(b * 2 + 0, qp, r1sq, r2sq, 0, wid, lane, sm1, sm2);
    __syncthreads();

    int c1 = block_extract<NGP / 256>(sm1, NS1, lane, wid, sl1, 0, 0, s_tot);
    int c2 = block_extract<NGP / 256>(sm2, NS2, lane, wid, sl2, 0, 0, s_tot);

    if (c1 < NS1 || c2 < NS2) {
        // Tail: re-zero full mask range, build over [DPRE, NPTS), append.
        for (int i = tid; i < NGT; i += 256) { sm1[i] = 0u; sm2[i] = 0u; }
        __syncthreads();
        sparse_mask_build(b * 2 + 1, qp, r1sq, r2sq, DPRE, wid, lane, sm1, sm2);
        __syncthreads();
        c1 = block_extract<NGT / 256>(sm1, NS1, lane, wid, sl1, c1, DPRE, s_tot);
        c2 = block_extract<NGT / 256>(sm2, NS2, lane, wid, sl2, c2, DPRE, s_tot);
    }

    // Padded write (reference: invalid -> first element, or 0 if none).
    if (wid == 0) {
        int* g1 = g_lists + q * 96;
        int* g2 = g1 + NS1;
        const int n1 = min(c1, NS1), n2 = min(c2, NS2);
        const int f1 = (n1 > 0) ? sl1[0] : 0;
        const int f2 = (n2 > 0) ? sl2[0] : 0;
        g1[lane] = (lane < n1) ? sl1[lane] : f1;
#pragma unroll
        for (int j = 0; j < 2; j++) {
            const int i = lane + j * 32;
            g2[i] = (i < n2) ? sl2[i] : f2;
        }
    }
}

// ---------------------------------------------------------------------------
// Kernel 4: MLP (R10/R11 version — w3 pre-packed, no smem transpose preamble).
// ---------------------------------------------------------------------------
#define INVC 0.9999950000374997f

__device__ __forceinline__ void mlp_point(
    float gx, float gy, float gz, float qx, float qy, float qz,
    const float* __restrict__ sA, const float* __restrict__ scA, const float* __restrict__ biA,
    const float* __restrict__ sB, const float* __restrict__ scB, const float* __restrict__ biB,
    float f[32])
{
    const float x0 = gx - qx, x1 = gy - qy, x2 = gz - qz;
    float a[16];
#pragma unroll
    for (int o = 0; o < 16; o++) {
        const float* w = sA + o * 6;
        float y = x0 * w[0];
        y = fmaf(x1, w[1], y);
        y = fmaf(x2, w[2], y);
        y = fmaf(gx, w[3], y);
        y = fmaf(gy, w[4], y);
        y = fmaf(gz, w[5], y);
        a[o] = fmaxf(fmaf(y, scA[o], biA[o]), 0.0f);
    }
#pragma unroll
    for (int o = 0; o < 32; o++) {
        const float* w = sB + o * 16;
        float y = 0.0f;
#pragma unroll
        for (int c = 0; c < 16; c++) y = fmaf(a[c], w[c], y);
        f[o] = fmaxf(f[o], fmaxf(fmaf(y, scB[o], biB[o]), 0.0f));
    }
}

__device__ __forceinline__ void warp_max32(float f[32]) {
#pragma unroll
    for (int o = 0; o < 32; o++) {
        float v = f[o];
        v = fmaxf(v, __shfl_xor_sync(0xffffffffu, v, 16));
        v = fmaxf(v, __shfl_xor_sync(0xffffffffu, v, 8));
        v = fmaxf(v, __shfl_xor_sync(0xffffffffu, v, 4));
        v = fmaxf(v, __shfl_xor_sync(0xffffffffu, v, 2));
        v = fmaxf(v, __shfl_xor_sync(0xffffffffu, v, 1));
        f[o] = v;
    }
}

__global__ __launch_bounds__(256) void mlp_kernel(
    const float* __restrict__ w1a, const float* __restrict__ g1a, const float* __restrict__ b1a,
    const float* __restrict__ w1b, const float* __restrict__ g1b, const float* __restrict__ b1b,
    const float* __restrict__ w2a, const float* __restrict__ g2a, const float* __restrict__ b2a,
    const float* __restrict__ w2b, const float* __restrict__ g2b, const float* __restrict__ b2b,
    const float* __restrict__ b3,
    float* __restrict__ out)
{
    __shared__ float s_w1a[96],  s_w2a[96];
    __shared__ float s_w1b[512], s_w2b[512];
    __shared__ float s_sc1a[16], s_bi1a[16], s_sc2a[16], s_bi2a[16];
    __shared__ float s_sc1b[32], s_bi1b[32], s_sc2b[32], s_bi2b[32];

    const int tid = threadIdx.x;
    for (int i = tid; i < 96; i += 256)  { s_w1a[i] = w1a[i]; s_w2a[i] = w2a[i]; }
    for (int i = tid; i < 512; i += 256) { s_w1b[i] = w1b[i]; s_w2b[i] = w2b[i]; }
    if (tid < 16) {
        s_sc1a[tid] = g1a[tid] * INVC; s_bi1a[tid] = b1a[tid];
        s_sc2a[tid] = g2a[tid] * INVC; s_bi2a[tid] = b2a[tid];
    } else if (tid < 48) {
        const int i = tid - 16;
        s_sc1b[i] = g1b[i] * INVC; s_bi1b[i] = b1b[i];
        s_sc2b[i] = g2b[i] * INVC; s_bi2b[i] = b2b[i];
    }
    __syncthreads();

    const int lane = tid & 31;
    const int wid  = tid >> 5;
    const int q    = blockIdx.x * 8 + wid;
    int b;
    const int fi = query_flat_index(q, b);

    const float4* __restrict__ P4 = g_pts4 + (size_t)b * NPTS;
    const float4 qp = __ldg(P4 + fi);
    const float qx = qp.x, qy = qp.y, qz = qp.z;

    const int* lst = g_lists + q * 96;
    const int i0 = __ldg(lst + lane);
    const int i1 = __ldg(lst + NS1 + lane);
    const int i2 = __ldg(lst + NS1 + 32 + lane);
    const float4 n0 = __ldg(P4 + i0);
    const float4 n1 = __ldg(P4 + i1);
    const float4 n2 = __ldg(P4 + i2);

    float acc0 = __ldg(b3 + lane +  0);
    float acc1 = __ldg(b3 + lane + 32);
    float acc2 = __ldg(b3 + lane + 64);
    float acc3 = __ldg(b3 + lane + 96);

    {   // branch 1 (S=32)
        float f[32];
#pragma unroll
        for (int o = 0; o < 32; o++) f[o] = 0.0f;
        mlp_point(n0.x, n0.y, n0.z, qx, qy, qz, s_w1a, s_sc1a, s_bi1a, s_w1b, s_sc1b, s_bi1b, f);
        warp_max32(f);
#pragma unroll
        for (int c = 0; c < 32; c++) {
            const float4 w = __ldg(g_w3t4 + c * 32 + lane);
            acc0 = fmaf(f[c], w.x, acc0);
            acc1 = fmaf(f[c], w.y, acc1);
            acc2 = fmaf(f[c], w.z, acc2);
            acc3 = fmaf(f[c], w.w, acc3);
        }
    }
    {   // branch 2 (S=64)
        float f[32];
#pragma unroll
        for (int o = 0; o < 32; o++) f[o] = 0.0f;
        mlp_point(n1.x, n1.y, n1.z, qx, qy, qz, s_w2a, s_sc2a, s_bi2a, s_w2b, s_sc2b, s_bi2b, f);
        mlp_point(n2.x, n2.y, n2.z, qx, qy, qz, s_w2a, s_sc2a, s_bi2a, s_w2b, s_sc2b, s_bi2b, f);
        warp_max32(f);
#pragma unroll
        for (int c = 0; c < 32; c++) {
            const float4 w = __ldg(g_w3t4 + (c + 32) * 32 + lane);
            acc0 = fmaf(f[c], w.x, acc0);
            acc1 = fmaf(f[c], w.y, acc1);
            acc2 = fmaf(f[c], w.z, acc2);
            acc3 = fmaf(f[c], w.w, acc3);
        }
    }
    const size_t ob = (size_t)q * NOUT;
    out[ob + lane +  0] = acc0;
    out[ob + lane + 32] = acc1;
    out[ob + lane + 64] = acc2;
    out[ob + lane + 96] = acc3;
}

extern "C" void kernel_launch(void* const* d_in, const int* in_sizes, int n_in,
                              void* d_out, int out_size) {
    const float* pts = (const float*)d_in[0];
    const float* w1a = (const float*)d_in[1];
    const float* g1a = (const float*)d_in[2];
    const float* b1a = (const float*)d_in[3];
    const float* w1b = (const float*)d_in[4];
    const float* g1b = (const float*)d_in[5];
    const float* b1b = (const float*)d_in[6];
    const float* w2a = (const float*)d_in[7];
    const float* g2a = (const float*)d_in[8];
    const float* b2a = (const float*)d_in[9];
    const float* w2b = (const float*)d_in[10];
    const float* g2b = (const float*)d_in[11];
    const float* b2b = (const float*)d_in[12];
    const float* w3  = (const float*)d_in[13];
    const float* b3  = (const float*)d_in[14];
    float* out = (float*)d_out;

    static void* hist_ptr = nullptr;
    if (!hist_ptr) cudaGetSymbolAddress(&hist_ptr, g_hist);

    cudaMemsetAsync(hist_ptr, 0, sizeof(int) * NBATCH * 2 * NCELL);
    prep_kernel<<<NBATCH * NPTS / 256 + 8, 256>>>(pts, w3);
    scan_kernel<<<NBATCH * 2, 1024>>>();
    scatter_kernel<<<NBATCH * NPTS / 256, 256>>>();
    ballquery_kernel<<<NBATCH * NQ, 256>>>();
    mlp_kernel<<<NBATCH * NQ / 8, 256>>>(w1a, g1a, b1a, w1b, g1b, b1b,
                                         w2a, g2a, b2a, w2b, g2b, b2b, b3, out);
}

// round 13
// speedup vs baseline: 1.6212x; 1.0690x over previous
#include <cuda_runtime.h>
#include <cstdint>

#define NPTS    65536
#define NQ      1024
#define NBATCH  2
#define NS1     32
#define NS2     64
#define NOUT    128
#define NSLAB   4
#define SLABPTS 16384               // points per index slab
#define NW      (SLABPTS / 32)      // 512 mask words per slab
#define NCELL   1000                // 10x10x10 cells
#define RP      0.201f              // r2 + margin for y/z cell boxes

static __device__ float4 g_pts4[NBATCH * NPTS];          // (x,y,z,|p|^2) by original idx
static __device__ float4 g_w3t4[64 * 32];                // [c][lane] -> outputs o=lane+32k
static __device__ int    g_hist[NBATCH * NSLAB][NCELL];
static __device__ int    g_cellstart[NBATCH * NSLAB][NCELL + 1];
static __device__ int    g_cursor[NBATCH * NSLAB][NCELL];
static __device__ float4 g_sp[(size_t)NBATCH * NSLAB * SLABPTS];  // binned points
static __device__ int    g_si[(size_t)NBATCH * NSLAB * SLABPTS];  // batch-local original idx
static __device__ int    g_lists[NBATCH * NQ * 96];      // [l1(32)|l2(64)]

__device__ __forceinline__ float sq3_rn(float x, float y, float z) {
    return __fadd_rn(__fadd_rn(__fmul_rn(x, x), __fmul_rn(y, y)), __fmul_rn(z, z));
}

__device__ __forceinline__ int query_flat_index(int q, int& b) {
    b = q >> 10;
    const int m = q & 1023;
    return (4 + 8 * (m >> 5)) * 256 + (4 + 8 * (m & 31));
}

__device__ __forceinline__ void radii(float& r1sq, float& r2sq) {
    r1sq = __fmul_rn(0.1f, 0.1f);
    r2sq = __fmul_rn(0.2f, 0.2f);
}

// d2 with the exact rounding order of the reference.
__device__ __forceinline__ float dist2_rn(float4 pt, float4 qp) {
    const float dot = __fadd_rn(__fadd_rn(__fmul_rn(pt.x, qp.x), __fmul_rn(pt.y, qp.y)),
                                __fmul_rn(pt.z, qp.z));
    return __fadd_rn(__fadd_rn(qp.w, pt.w), __fmul_rn(-2.0f, dot));
}

__device__ __forceinline__ int cell_of(float x, float y, float z) {
    const int cx = min(9, (int)(x * 10.0f));
    const int cy = min(9, (int)(y * 10.0f));
    const int cz = min(9, (int)(z * 10.0f));
    return (cz * 10 + cy) * 10 + cx;
}

// ---------------------------------------------------------------------------
// Kernel 0: pack pts; histogram cells per (batch, index-slab); pack w3.
// ---------------------------------------------------------------------------
__global__ __launch_bounds__(256) void prep_kernel(const float* __restrict__ pts,
                                                   const float* __restrict__ w3) {
    const int blk = blockIdx.x;
    if (blk < NBATCH * NPTS / 256) {
        const int i = blk * 256 + threadIdx.x;   // 0..131071
        const float x = __ldg(pts + 3 * i + 0);
        const float y = __ldg(pts + 3 * i + 1);
        const float z = __ldg(pts + 3 * i + 2);
        g_pts4[i] = make_float4(x, y, z, sq3_rn(x, y, z));
        const int b = i >> 16, pi = i & (NPTS - 1);
        atomicAdd(&g_hist[b * NSLAB + (pi >> 14)][cell_of(x, y, z)], 1);
    } else {
        const int i = (blk - NBATCH * NPTS / 256) * 256 + threadIdx.x;
        if (i < 64 * 32) {
            const int c = i >> 5, j = i & 31;
            g_w3t4[i] = make_float4(__ldg(w3 + (j +  0) * 64 + c),
                                    __ldg(w3 + (j + 32) * 64 + c),
                                    __ldg(w3 + (j + 64) * 64 + c),
                                    __ldg(w3 + (j + 96) * 64 + c));
        }
    }
}

// ---------------------------------------------------------------------------
// Kernel 1: exclusive scan of per-slab histograms.
// ---------------------------------------------------------------------------
__global__ __launch_bounds__(1024) void scan_kernel() {
    __shared__ int buf[2][1024];
    const int br = blockIdx.x, tid = threadIdx.x;
    int v = (tid < NCELL) ? g_hist[br][tid] : 0;
    buf[0][tid] = v;
    __syncthreads();
    int src = 0;
    for (int d = 1; d < 1024; d <<= 1) {
        int t = buf[src][tid];
        if (tid >= d) t += buf[src][tid - d];
        __syncthreads();
        buf[src ^ 1][tid] = t;
        src ^= 1;
        __syncthreads();
    }
    const int excl = (tid == 0) ? 0 : buf[src][tid - 1];
    if (tid <= NCELL) g_cellstart[br][tid] = excl;
    if (tid < NCELL)  g_cursor[br][tid] = excl;
}

// ---------------------------------------------------------------------------
// Kernel 2: scatter points into binned slabs.
// ---------------------------------------------------------------------------
__global__ __launch_bounds__(256) void scatter_kernel() {
    const int i = blockIdx.x * 256 + threadIdx.x;   // 0..131071
    const int b = i >> 16, pi = i & (NPTS - 1);
    const float4 p = g_pts4[i];
    const int br = b * NSLAB + (pi >> 14);
    const int pos = atomicAdd(&g_cursor[br][cell_of(p.x, p.y, p.z)], 1);
    g_sp[(size_t)br * SLABPTS + pos] = p;
    g_si[(size_t)br * SLABPTS + pos] = pi;
}

// ---------------------------------------------------------------------------
// Append first-K set bits (ascending) from nwords mask words starting at cnt0.
// Warp-collective, early exit per 32-word chunk. Returns total count seen.
// ---------------------------------------------------------------------------
__device__ __forceinline__ int extract_append(
    const unsigned* __restrict__ mask, int nwords, int K, int lane,
    int* __restrict__ list, int cnt0, int idx_base)
{
    int cnt = cnt0;
    for (int w0 = 0; w0 < nwords && cnt < K; w0 += 32) {
        const unsigned v = mask[w0 + lane];
        const int pc = __popc(v);
        int pre = pc;
#pragma unroll
        for (int d = 1; d < 32; d <<= 1) {
            const int t = __shfl_up_sync(0xffffffffu, pre, d);
            if (lane >= d) pre += t;
        }
        int p = cnt + (pre - pc);
        unsigned vv = v;
        while (vv && p < K) {
            const int bit = __ffs(vv) - 1;
            list[p] = idx_base + (w0 + lane) * 32 + bit;
            p++; vv &= vv - 1;
        }
        cnt += __shfl_sync(0xffffffffu, pre, 31);
    }
    return cnt;
}

// ---------------------------------------------------------------------------
// Sphere-trimmed candidate loop over one slab; 2 warps split rows.
// Sets bits (pi & 16383) in the shared per-query masks.
// ---------------------------------------------------------------------------
__device__ __forceinline__ void build_slab(
    int br, float4 qp, float r1sq, float r2sq,
    int wid, int lane, unsigned* __restrict__ m1, unsigned* __restrict__ m2)
{
    const float4* __restrict__ sp = g_sp + (size_t)br * SLABPTS;
    const int*    __restrict__ si = g_si + (size_t)br * SLABPTS;
    const int*    __restrict__ cs = g_cellstart[br];

    const int cy0 = max(0, (int)((qp.y - RP) * 10.0f));
    const int cy1 = min(9, (int)((qp.y + RP) * 10.0f));
    const int cz0 = max(0, (int)((qp.z - RP) * 10.0f));
    const int cz1 = min(9, (int)((qp.z + RP) * 10.0f));
    const int ny = cy1 - cy0 + 1;
    const int nrows = (cz1 - cz0 + 1) * ny;

    for (int rr = wid; rr < nrows; rr += 2) {
        const int cz = cz0 + rr / ny, cy = cy0 + rr % ny;
        const float dy = fmaxf(0.0f, fmaxf(cy * 0.1f - qp.y, qp.y - (cy + 1) * 0.1f));
        const float dz = fmaxf(0.0f, fmaxf(cz * 0.1f - qp.z, qp.z - (cz + 1) * 0.1f));
        const float dyz2 = dy * dy + dz * dz;
        if (dyz2 > r2sq + 1e-4f) continue;                 // row outside ball
        const float w = sqrtf(fmaxf(r2sq - dyz2, 0.0f)) + 2e-3f;   // conservative half-width
        const int cx0 = max(0, (int)((qp.x - w) * 10.0f));
        const int cx1 = min(9, (int)((qp.x + w) * 10.0f));
        const int row = (cz * 10 + cy) * 10;
        const int s = cs[row + cx0];
        const int e = cs[row + cx1 + 1];                   // x-cells contiguous
        for (int j = s + lane; j < e; j += 32) {
            const float4 pt = __ldg(sp + j);
            const float d2 = dist2_rn(pt, qp);
            if (d2 < r2sq) {
                const int bp = __ldg(si + j) & (SLABPTS - 1);
                atomicOr(&m2[bp >> 5], 1u << (bp & 31));
                if (d2 < r1sq) atomicOr(&m1[bp >> 5], 1u << (bp & 31));
            }
        }
    }
}

// ---------------------------------------------------------------------------
// Kernel 3: ball query. Block = 64 threads = 1 query (2 warps). Slab loop with
// early exit; warps split build rows, then extract m1/m2 in parallel.
// ---------------------------------------------------------------------------
__global__ __launch_bounds__(64) void ballquery_kernel() {
    __shared__ unsigned m1[NW], m2[NW];    // 4 KB
    __shared__ int sl1[NS1], sl2[NS2], scnt[2];

    const int tid = threadIdx.x, lane = tid & 31, wid = tid >> 5;
    const int q = blockIdx.x, b = q >> 10;
    int bb;
    const int fi = query_flat_index(q, bb);
    const float4 qp = __ldg(g_pts4 + (size_t)b * NPTS + fi);
    float r1sq, r2sq; radii(r1sq, r2sq);

    int c1 = 0, c2 = 0;
    for (int s = 0; s < NSLAB; s++) {
        for (int i = tid; i < NW; i += 64) { m1[i] = 0u; m2[i] = 0u; }
        __syncthreads();
        build_slab(b * NSLAB + s, qp, r1sq, r2sq, wid, lane, m1, m2);
        __syncthreads();
        if (wid == 0) {
            const int t = extract_append(m1, NW, NS1, lane, sl1, c1, s * SLABPTS);
            if (lane == 0) scnt[0] = t;
        } else {
            const int t = extract_append(m2, NW, NS2, lane, sl2, c2, s * SLABPTS);
            if (lane == 0) scnt[1] = t;
        }
        __syncthreads();
        c1 = scnt[0]; c2 = scnt[1];
        if (c1 >= NS1 && c2 >= NS2) break;
    }

    // Padded write (reference: invalid -> first element, or 0 if none).
    if (wid == 0) {
        int* g1 = g_lists + q * 96;
        const int n1 = min(c1, NS1);
        const int f1 = (n1 > 0) ? sl1[0] : 0;
        g1[lane] = (lane < n1) ? sl1[lane] : f1;
    } else {
        int* g2 = g_lists + q * 96 + NS1;
        const int n2 = min(c2, NS2);
        const int f2 = (n2 > 0) ? sl2[0] : 0;
#pragma unroll
        for (int j = 0; j < 2; j++) {
            const int i = lane + j * 32;
            g2[i] = (i < n2) ? sl2[i] : f2;
        }
    }
}

// ---------------------------------------------------------------------------
// Kernel 4: MLP (R12 version — w3 pre-packed, no smem transpose preamble).
// ---------------------------------------------------------------------------
#define INVC 0.9999950000374997f

__device__ __forceinline__ void mlp_point(
    float gx, float gy, float gz, float qx, float qy, float qz,
    const float* __restrict__ sA, const float* __restrict__ scA, const float* __restrict__ biA,
    const float* __restrict__ sB, const float* __restrict__ scB, const float* __restrict__ biB,
    float f[32])
{
    const float x0 = gx - qx, x1 = gy - qy, x2 = gz - qz;
    float a[16];
#pragma unroll
    for (int o = 0; o < 16; o++) {
        const float* w = sA + o * 6;
        float y = x0 * w[0];
        y = fmaf(x1, w[1], y);
        y = fmaf(x2, w[2], y);
        y = fmaf(gx, w[3], y);
        y = fmaf(gy, w[4], y);
        y = fmaf(gz, w[5], y);
        a[o] = fmaxf(fmaf(y, scA[o], biA[o]), 0.0f);
    }
#pragma unroll
    for (int o = 0; o < 32; o++) {
        const float* w = sB + o * 16;
        float y = 0.0f;
#pragma unroll
        for (int c = 0; c < 16; c++) y = fmaf(a[c], w[c], y);
        f[o] = fmaxf(f[o], fmaxf(fmaf(y, scB[o], biB[o]), 0.0f));
    }
}

__device__ __forceinline__ void warp_max32(float f[32]) {
#pragma unroll
    for (int o = 0; o < 32; o++) {
        float v = f[o];
        v = fmaxf(v, __shfl_xor_sync(0xffffffffu, v, 16));
        v = fmaxf(v, __shfl_xor_sync(0xffffffffu, v, 8));
        v = fmaxf(v, __shfl_xor_sync(0xffffffffu, v, 4));
        v = fmaxf(v, __shfl_xor_sync(0xffffffffu, v, 2));
        v = fmaxf(v, __shfl_xor_sync(0xffffffffu, v, 1));
        f[o] = v;
    }
}

__global__ __launch_bounds__(256) void mlp_kernel(
    const float* __restrict__ w1a, const float* __restrict__ g1a, const float* __restrict__ b1a,
    const float* __restrict__ w1b, const float* __restrict__ g1b, const float* __restrict__ b1b,
    const float* __restrict__ w2a, const float* __restrict__ g2a, const float* __restrict__ b2a,
    const float* __restrict__ w2b, const float* __restrict__ g2b, const float* __restrict__ b2b,
    const float* __restrict__ b3,
    float* __restrict__ out)
{
    __shared__ float s_w1a[96],  s_w2a[96];
    __shared__ float s_w1b[512], s_w2b[512];
    __shared__ float s_sc1a[16], s_bi1a[16], s_sc2a[16], s_bi2a[16];
    __shared__ float s_sc1b[32], s_bi1b[32], s_sc2b[32], s_bi2b[32];

    const int tid = threadIdx.x;
    for (int i = tid; i < 96; i += 256)  { s_w1a[i] = w1a[i]; s_w2a[i] = w2a[i]; }
    for (int i = tid; i < 512; i += 256) { s_w1b[i] = w1b[i]; s_w2b[i] = w2b[i]; }
    if (tid < 16) {
        s_sc1a[tid] = g1a[tid] * INVC; s_bi1a[tid] = b1a[tid];
        s_sc2a[tid] = g2a[tid] * INVC; s_bi2a[tid] = b2a[tid];
    } else if (tid < 48) {
        const int i = tid - 16;
        s_sc1b[i] = g1b[i] * INVC; s_bi1b[i] = b1b[i];
        s_sc2b[i] = g2b[i] * INVC; s_bi2b[i] = b2b[i];
    }
    __syncthreads();

    const int lane = tid & 31;
    const int wid  = tid >> 5;
    const int q    = blockIdx.x * 8 + wid;
    int b;
    const int fi = query_flat_index(q, b);

    const float4* __restrict__ P4 = g_pts4 + (size_t)b * NPTS;
    const float4 qp = __ldg(P4 + fi);
    const float qx = qp.x, qy = qp.y, qz = qp.z;

    const int* lst = g_lists + q * 96;
    const int i0 = __ldg(lst + lane);
    const int i1 = __ldg(lst + NS1 + lane);
    const int i2 = __ldg(lst + NS1 + 32 + lane);
    const float4 n0 = __ldg(P4 + i0);
    const float4 n1 = __ldg(P4 + i1);
    const float4 n2 = __ldg(P4 + i2);

    float acc0 = __ldg(b3 + lane +  0);
    float acc1 = __ldg(b3 + lane + 32);
    float acc2 = __ldg(b3 + lane + 64);
    float acc3 = __ldg(b3 + lane + 96);

    {   // branch 1 (S=32)
        float f[32];
#pragma unroll
        for (int o = 0; o < 32; o++) f[o] = 0.0f;
        mlp_point(n0.x, n0.y, n0.z, qx, qy, qz, s_w1a, s_sc1a, s_bi1a, s_w1b, s_sc1b, s_bi1b, f);
        warp_max32(f);
#pragma unroll
        for (int c = 0; c < 32; c++) {
            const float4 w = __ldg(g_w3t4 + c * 32 + lane);
            acc0 = fmaf(f[c], w.x, acc0);
            acc1 = fmaf(f[c], w.y, acc1);
            acc2 = fmaf(f[c], w.z, acc2);
            acc3 = fmaf(f[c], w.w, acc3);
        }
    }
    {   // branch 2 (S=64)
        float f[32];
#pragma unroll
        for (int o = 0; o < 32; o++) f[o] = 0.0f;
        mlp_point(n1.x, n1.y, n1.z, qx, qy, qz, s_w2a, s_sc2a, s_bi2a, s_w2b, s_sc2b, s_bi2b, f);
        mlp_point(n2.x, n2.y, n2.z, qx, qy, qz, s_w2a, s_sc2a, s_bi2a, s_w2b, s_sc2b, s_bi2b, f);
        warp_max32(f);
#pragma unroll
        for (int c = 0; c < 32; c++) {
            const float4 w = __ldg(g_w3t4 + (c + 32) * 32 + lane);
            acc0 = fmaf(f[c], w.x, acc0);
            acc1 = fmaf(f[c], w.y, acc1);
            acc2 = fmaf(f[c], w.z, acc2);
            acc3 = fmaf(f[c], w.w, acc3);
        }
    }
    const size_t ob = (size_t)q * NOUT;
    out[ob + lane +  0] = acc0;
    out[ob + lane + 32] = acc1;
    out[ob + lane + 64] = acc2;
    out[ob + lane + 96] = acc3;
}

extern "C" void kernel_launch(void* const* d_in, const int* in_sizes, int n_in,
                              void* d_out, int out_size) {
    const float* pts = (const float*)d_in[0];
    const float* w1a = (const float*)d_in[1];
    const float* g1a = (const float*)d_in[2];
    const float* b1a = (const float*)d_in[3];
    const float* w1b = (const float*)d_in[4];
    const float* g1b = (const float*)d_in[5];
    const float* b1b = (const float*)d_in[6];
    const float* w2a = (const float*)d_in[7];
    const float* g2a = (const float*)d_in[8];
    const float* b2a = (const float*)d_in[9];
    const float* w2b = (const float*)d_in[10];
    const float* g2b = (const float*)d_in[11];
    const float* b2b = (const float*)d_in[12];
    const float* w3  = (const float*)d_in[13];
    const float* b3  = (const float*)d_in[14];
    float* out = (float*)d_out;

    static void* hist_ptr = nullptr;
    if (!hist_ptr) cudaGetSymbolAddress(&hist_ptr, g_hist);

    cudaMemsetAsync(hist_ptr, 0, sizeof(int) * NBATCH * NSLAB * NCELL);
    prep_kernel<<<NBATCH * NPTS / 256 + 8, 256>>>(pts, w3);
    scan_kernel<<<NBATCH * NSLAB, 1024>>>();
    scatter_kernel<<<NBATCH * NPTS / 256, 256>>>();
    ballquery_kernel<<<NBATCH * NQ, 64>>>();
    mlp_kernel<<<NBATCH * NQ / 8, 256>>>(w1a, g1a, b1a, w1b, g1b, b1b,
                                         w2a, g2a, b2a, w2b, g2b, b2b, b3, out);
}